// round 10
// baseline (speedup 1.0000x reference)
#include <cuda_runtime.h>
#include <cuda_fp16.h>
#include <math.h>

// Problem constants
#define Bsz   32
#define Tn    512
#define Jn    25
#define DENC  256
#define Hn    512
#define G4    2048      // 4*H
#define NB    128       // persistent recurrence grid (co-resident)
#define NB2   64        // blocks per direction

// ---------------- scratch (device globals; no allocations) ----------------
__device__ float    g_enc [Bsz * Tn * DENC];
__device__ float    g_xg  [2L * Tn * Bsz * G4];           // [d][t][b][4H]
__device__ float    g_out0[Bsz * Tn * 2 * Hn];            // [b][t][2H]
__device__ float    g_out1[Bsz * Tn * 2 * Hn];
__device__ __align__(16) __half g_h[2][2 * Bsz * Hn];     // fp16 h, double-buffered
__device__ unsigned g_bar_cnt[64];                        // [d*32]: separate lines
__device__ unsigned g_bar_gen[64];

// ---------------- helpers --------------------------------------------------
__device__ __forceinline__ unsigned f2tf(float x) {
    unsigned u;
    asm("cvt.rna.tf32.f32 %0, %1;" : "=r"(u) : "f"(x));
    return u;
}

__device__ __forceinline__ void mma_tf32(float* c,
                                         unsigned a0, unsigned a1,
                                         unsigned a2, unsigned a3,
                                         unsigned b0, unsigned b1) {
    asm("mma.sync.aligned.m16n8k8.row.col.f32.tf32.tf32.f32 "
        "{%0,%1,%2,%3}, {%4,%5,%6,%7}, {%8,%9}, {%0,%1,%2,%3};"
        : "+f"(c[0]), "+f"(c[1]), "+f"(c[2]), "+f"(c[3])
        : "r"(a0), "r"(a1), "r"(a2), "r"(a3), "r"(b0), "r"(b1));
}

// ---------------- per-direction grid barrier (NB2 blocks each) ------------
__device__ __forceinline__ void grid_sync_dir(int d) {
    __threadfence();
    __syncthreads();
    if (threadIdx.x == 0) {
        volatile unsigned* vg = &g_bar_gen[d * 32];
        unsigned gen = *vg;
        if (atomicAdd(&g_bar_cnt[d * 32], 1u) == NB2 - 1) {
            g_bar_cnt[d * 32] = 0;
            __threadfence();
            *vg = gen + 1;
        } else {
            while (*vg == gen) { __nanosleep(32); }
        }
    }
    __syncthreads();
    __threadfence();
}

// ---------------- zero the output buffers ---------------------------------
__global__ void zero_kernel() {
    const int n4 = (Bsz * Tn * 2 * Hn) / 4;
    float4 z = make_float4(0.f, 0.f, 0.f, 0.f);
    for (int i = blockIdx.x * blockDim.x + threadIdx.x; i < n4;
         i += gridDim.x * blockDim.x) {
        reinterpret_cast<float4*>(g_out0)[i] = z;
        reinterpret_cast<float4*>(g_out1)[i] = z;
    }
}

// ---------------- encoder: relu(masked_xy @ W^T + b) ----------------------
__global__ void enc_kernel(const float* __restrict__ feats,
                           const float* __restrict__ W,
                           const float* __restrict__ bias) {
    __shared__ float xs[2 * Jn];
    const int bt  = blockIdx.x;
    const int tid = threadIdx.x;
    const float* f = feats + (size_t)bt * (Jn * 3);
    if (tid < Jn) {
        float c = (f[tid * 3 + 2] > 0.1f) ? 1.f : 0.f;
        xs[tid * 2 + 0] = f[tid * 3 + 0] * c;
        xs[tid * 2 + 1] = f[tid * 3 + 1] * c;
    }
    __syncthreads();
    const float* w = W + tid * (2 * Jn);
    float s = bias[tid];
#pragma unroll
    for (int k = 0; k < 2 * Jn; ++k) s += xs[k] * w[k];
    g_enc[(size_t)bt * DENC + tid] = fmaxf(s, 0.f);
}

// ---------------- input projection GEMM (tf32, double-buffered) -----------
// out_xg[d][t][b][g] = A[m=b*T+t,:K] . W[d][g,:K] + bias[d][g]
// block 128x128, 8 warps (2m x 4n), k-tile 16, ping-pong smem (1 sync/tile)
__global__ void __launch_bounds__(256)
proj_gemm(int srcSel, int K, const float* __restrict__ W,
          const float* __restrict__ bias) {
    const float* A  = srcSel ? g_out0 : g_enc;
    const int d  = blockIdx.z;
    const float* Wd = W + (size_t)d * G4 * K;
    const float* bd = bias + d * G4;
    const int n0 = blockIdx.x * 128;
    const int m0 = blockIdx.y * 128;

    __shared__ unsigned As[2][128 * 20];   // [m][k], stride 20 (conflict-free)
    __shared__ unsigned Ws[2][128 * 20];   // [n][k]

    const int tid  = threadIdx.x;
    const int lane = tid & 31;
    const int wid  = tid >> 5;
    const int wm   = (wid >> 2) * 64;
    const int wn   = (wid & 3) * 32;

    float acc[4][4][4];
#pragma unroll
    for (int mt = 0; mt < 4; ++mt)
#pragma unroll
        for (int nt = 0; nt < 4; ++nt)
#pragma unroll
            for (int i = 0; i < 4; ++i) acc[mt][nt][i] = 0.f;

    const int r0  = tid >> 2;
    const int kq0 = (tid & 3) << 2;

    float4 pa0, pa1, pw0, pw1;
    pa0 = *reinterpret_cast<const float4*>(A  + (size_t)(m0 + r0)      * K + kq0);
    pa1 = *reinterpret_cast<const float4*>(A  + (size_t)(m0 + r0 + 64) * K + kq0);
    pw0 = *reinterpret_cast<const float4*>(Wd + (size_t)(n0 + r0)      * K + kq0);
    pw1 = *reinterpret_cast<const float4*>(Wd + (size_t)(n0 + r0 + 64) * K + kq0);

    const int KT = K >> 4;
    for (int kt = 0; kt < KT; ++kt) {
        const int p = kt & 1;
        {
            uint4 u;
            u.x = f2tf(pa0.x); u.y = f2tf(pa0.y); u.z = f2tf(pa0.z); u.w = f2tf(pa0.w);
            *reinterpret_cast<uint4*>(As[p] + r0 * 20 + kq0) = u;
            u.x = f2tf(pa1.x); u.y = f2tf(pa1.y); u.z = f2tf(pa1.z); u.w = f2tf(pa1.w);
            *reinterpret_cast<uint4*>(As[p] + (r0 + 64) * 20 + kq0) = u;
            u.x = f2tf(pw0.x); u.y = f2tf(pw0.y); u.z = f2tf(pw0.z); u.w = f2tf(pw0.w);
            *reinterpret_cast<uint4*>(Ws[p] + r0 * 20 + kq0) = u;
            u.x = f2tf(pw1.x); u.y = f2tf(pw1.y); u.z = f2tf(pw1.z); u.w = f2tf(pw1.w);
            *reinterpret_cast<uint4*>(Ws[p] + (r0 + 64) * 20 + kq0) = u;
        }
        __syncthreads();     // single barrier per tile (ping-pong buffers)

        if (kt + 1 < KT) {   // prefetch next tile while computing
            int kn = (kt + 1) << 4;
            pa0 = *reinterpret_cast<const float4*>(A  + (size_t)(m0 + r0)      * K + kn + kq0);
            pa1 = *reinterpret_cast<const float4*>(A  + (size_t)(m0 + r0 + 64) * K + kn + kq0);
            pw0 = *reinterpret_cast<const float4*>(Wd + (size_t)(n0 + r0)      * K + kn + kq0);
            pw1 = *reinterpret_cast<const float4*>(Wd + (size_t)(n0 + r0 + 64) * K + kn + kq0);
        }

        const unsigned* Ab = As[p];
        const unsigned* Bb = Ws[p];
#pragma unroll
        for (int kk = 0; kk < 16; kk += 8) {
            unsigned af[4][4], bf[4][2];
#pragma unroll
            for (int mt = 0; mt < 4; ++mt) {
                const unsigned* pp = Ab + (wm + mt * 16 + (lane >> 2)) * 20 + kk + (lane & 3);
                af[mt][0] = pp[0];
                af[mt][1] = pp[8 * 20];
                af[mt][2] = pp[4];
                af[mt][3] = pp[8 * 20 + 4];
            }
#pragma unroll
            for (int nt = 0; nt < 4; ++nt) {
                const unsigned* pp = Bb + (wn + nt * 8 + (lane >> 2)) * 20 + kk + (lane & 3);
                bf[nt][0] = pp[0];
                bf[nt][1] = pp[4];
            }
#pragma unroll
            for (int mt = 0; mt < 4; ++mt)
#pragma unroll
                for (int nt = 0; nt < 4; ++nt)
                    mma_tf32(acc[mt][nt], af[mt][0], af[mt][1], af[mt][2], af[mt][3],
                             bf[nt][0], bf[nt][1]);
        }
    }

    // epilogue: bias + scatter to g_xg
#pragma unroll
    for (int mt = 0; mt < 4; ++mt) {
        int mrow0 = m0 + wm + mt * 16 + (lane >> 2);
#pragma unroll
        for (int nt = 0; nt < 4; ++nt) {
            int n = n0 + wn + nt * 8 + (lane & 3) * 2;
            float bv0 = bd[n], bv1 = bd[n + 1];
#pragma unroll
            for (int h = 0; h < 2; ++h) {
                int m  = mrow0 + h * 8;
                int t  = m & (Tn - 1);
                int bb = m >> 9;
                float* cp = g_xg + (((size_t)d * Tn + t) * Bsz + bb) * G4 + n;
                *reinterpret_cast<float2*>(cp) =
                    make_float2(acc[mt][nt][h * 2 + 0] + bv0,
                                acc[mt][nt][h * 2 + 1] + bv1);
            }
        }
    }
}

// ---------------- persistent bidirectional LSTM recurrence (tf32 MMA) -----
// R8 structure + two changes:
//  - h transported as fp16 (same 10-bit mantissa rounding as tf32; f16->f32
//    conversion is exact and bit-valid as a tf32 mma operand). Halves the
//    per-step L2 broadcast traffic (LTS-cap bound).
//  - per-direction grid barriers (64 arrivals instead of 128).
#define REC_SMEM ((32 * 516 + 32 * 136) * 4)
extern __shared__ unsigned smr[];

__global__ void __launch_bounds__(256, 1)
rec_kernel(const float* __restrict__ whh,      // [2][4H][H]
           const int*   __restrict__ lengths,
           int outSel) {
    unsigned* hs   = smr;                          // [32 b][516] tf32 bits
    float*    part = (float*)(smr + 32 * 516);     // [32 b][136]
    float* out = outSel ? g_out1 : g_out0;
    const float* xg = g_xg;

    const int tid  = threadIdx.x;
    const int lane = tid & 31;
    const int wid  = tid >> 5;
    const int bx   = blockIdx.x;
    const int d    = bx >> 6;
    const int j0   = (bx & 63) << 3;
    const int mb   = wid & 1;             // batch half
    const int kc   = wid >> 1;            // K chunk (0..3), 128 k each

    // stationary W fragments (B side): b0,b1 per (ks, nt=q)
    unsigned wb0[16][4], wb1[16][4];
    {
        const float* wdb = whh + (size_t)d * G4 * Hn;
#pragma unroll
        for (int ks = 0; ks < 16; ++ks)
#pragma unroll
            for (int nt = 0; nt < 4; ++nt) {
                const float* wp = wdb + (size_t)(nt * Hn + j0 + (lane >> 2)) * Hn
                                  + kc * 128 + ks * 8 + (lane & 3);
                wb0[ks][nt] = f2tf(wp[0]);
                wb1[ks][nt] = f2tf(wp[4]);
            }
    }

    // phase-2 identity: jj-major -> coalesced gmem
    const int jj = tid & 7;
    const int b2 = tid >> 3;              // 0..31
    const int len = lengths[b2];
    const int hidx = (d * Bsz + b2) * Hn + j0 + jj;
    float c_reg = 0.f;
    __half h_half = __float2half_rn(0.f);
    g_h[0][hidx] = h_half;

    grid_sync_dir(d);   // own dir's h buffer 0 zeroed

    for (int s = 0; s < Tn; ++s) {
        const int pr = s & 1, pw_ = pr ^ 1;
        const bool act = s < len;
        const int t = d ? (len - 1 - s) : s;

        // prefetch xg (32B-coalesced per (b,q) group)
        float xv0 = 0.f, xv1 = 0.f, xv2 = 0.f, xv3 = 0.f;
        if (act) {
            const float* xr = xg + (((size_t)d * Tn + t) * Bsz + b2) * G4 + j0 + jj;
            xv0 = xr[0];
            xv1 = xr[Hn];
            xv2 = xr[2 * Hn];
            xv3 = xr[3 * Hn];
        }

        // stage h (own dir, 32KB fp16) into smem as f32/tf32 bits
        {
            const __half* hsrc = g_h[pr] + d * Bsz * Hn;
#pragma unroll
            for (int i = 0; i < 8; ++i) {
                int f  = tid + i * 256;           // 0..2047 (8-half groups)
                int r  = f >> 6;                  // batch row 0..31
                int kq = (f & 63) << 3;           // k offset 0..504
                uint4 v = *reinterpret_cast<const uint4*>(hsrc + r * Hn + kq);
                const __half2* h2 = reinterpret_cast<const __half2*>(&v);
                float2 f0 = __half22float2(h2[0]);
                float2 f1 = __half22float2(h2[1]);
                float2 f2 = __half22float2(h2[2]);
                float2 f3 = __half22float2(h2[3]);
                uint4 o0, o1;
                o0.x = __float_as_uint(f0.x); o0.y = __float_as_uint(f0.y);
                o0.z = __float_as_uint(f1.x); o0.w = __float_as_uint(f1.y);
                o1.x = __float_as_uint(f2.x); o1.y = __float_as_uint(f2.y);
                o1.z = __float_as_uint(f3.x); o1.w = __float_as_uint(f3.y);
                *reinterpret_cast<uint4*>(hs + r * 516 + kq)     = o0;
                *reinterpret_cast<uint4*>(hs + r * 516 + kq + 4) = o1;
            }
        }
        __syncthreads();

        float acc[4][4];
#pragma unroll
        for (int nt = 0; nt < 4; ++nt)
#pragma unroll
            for (int i = 0; i < 4; ++i) acc[nt][i] = 0.f;

#pragma unroll
        for (int ks = 0; ks < 16; ++ks) {
            const unsigned* hp = hs + (mb * 16 + (lane >> 2)) * 516
                                 + kc * 128 + ks * 8 + (lane & 3);
            unsigned a0 = hp[0];
            unsigned a2 = hp[4];
            unsigned a1 = hp[8 * 516];
            unsigned a3 = hp[8 * 516 + 4];
#pragma unroll
            for (int nt = 0; nt < 4; ++nt)
                mma_tf32(acc[nt], a0, a1, a2, a3, wb0[ks][nt], wb1[ks][nt]);
        }

        // write K-chunk partials: part[batch][kc*32 + q*8 + jcol]
        {
            const int b_lo = mb * 16 + (lane >> 2);
            const int col  = kc * 32 + ((lane & 3) << 1);
#pragma unroll
            for (int nt = 0; nt < 4; ++nt) {
                float* pp = part + b_lo * 136 + col + nt * 8;
                *reinterpret_cast<float2*>(pp) =
                    make_float2(acc[nt][0], acc[nt][1]);
                *reinterpret_cast<float2*>(pp + 8 * 136) =
                    make_float2(acc[nt][2], acc[nt][3]);
            }
        }
        __syncthreads();

        // phase 2: reduce 4 K-chunk partials + gates (conflict-free reads)
        if (act) {
            const float* pb = part + b2 * 136 + jj;
            float gv[4];
#pragma unroll
            for (int q = 0; q < 4; ++q) {
                float v = (q == 0) ? xv0 : (q == 1) ? xv1 : (q == 2) ? xv2 : xv3;
#pragma unroll
                for (int k2 = 0; k2 < 4; ++k2)
                    v += pb[k2 * 32 + q * 8];
                gv[q] = v;
            }
            float ig = 1.f / (1.f + __expf(-gv[0]));
            float fg = 1.f / (1.f + __expf(-gv[1]));
            float gg = tanhf(gv[2]);
            float og = 1.f / (1.f + __expf(-gv[3]));
            c_reg = fg * c_reg + ig * gg;
            float hn = og * tanhf(c_reg);
            h_half = __float2half_rn(hn);
            out[((size_t)b2 * Tn + t) * (2 * Hn) + d * Hn + j0 + jj] = hn;
        }
        g_h[pw_][hidx] = h_half;   // frozen h re-written when inactive

        grid_sync_dir(d);
    }
}

// ---------------- mean pooling over valid length --------------------------
__global__ void pool_kernel(const int* __restrict__ lengths,
                            float* __restrict__ out) {
    const int c = blockIdx.x * 256 + threadIdx.x;
    const int b = blockIdx.y;
    const float* p = g_out1 + (size_t)b * Tn * (2 * Hn) + c;
    float s = 0.f;
    for (int t = 0; t < Tn; ++t) s += p[(size_t)t * (2 * Hn)];
    out[b * (2 * Hn) + c] = s / (float)lengths[b];
}

// ---------------- launch ---------------------------------------------------
extern "C" void kernel_launch(void* const* d_in, const int* in_sizes, int n_in,
                              void* d_out, int out_size) {
    const float* feats = (const float*)d_in[0];
    const int*   lens  = (const int*)  d_in[1];
    const float* encW  = (const float*)d_in[2];
    const float* encb  = (const float*)d_in[3];
    const float* wih0  = (const float*)d_in[4];
    const float* whh0  = (const float*)d_in[5];
    const float* b0    = (const float*)d_in[6];
    const float* wih1  = (const float*)d_in[7];
    const float* whh1  = (const float*)d_in[8];
    const float* b1    = (const float*)d_in[9];
    float* out = (float*)d_out;

    // opt-in to >48KB dynamic smem (attribute set, not an allocation)
    cudaFuncSetAttribute(rec_kernel,
                         cudaFuncAttributeMaxDynamicSharedMemorySize, REC_SMEM);

    zero_kernel<<<2048, 256>>>();
    enc_kernel<<<Bsz * Tn, 256>>>(feats, encW, encb);

    // layer 0: project (K=256) then scan
    {
        dim3 grid(16, 128, 2);
        proj_gemm<<<grid, 256>>>(0, DENC, wih0, b0);
        rec_kernel<<<NB, 256, REC_SMEM>>>(whh0, lens, 0);
    }
    // layer 1: project (K=1024) then scan
    {
        dim3 grid(16, 128, 2);
        proj_gemm<<<grid, 256>>>(1, 2 * Hn, wih1, b1);
        rec_kernel<<<NB, 256, REC_SMEM>>>(whh1, lens, 1);
    }

    dim3 pg(4, Bsz);
    pool_kernel<<<pg, 256>>>(lens, out);
}

// round 11
// speedup vs baseline: 1.0506x; 1.0506x over previous
#include <cuda_runtime.h>
#include <cuda_fp16.h>
#include <math.h>

// Problem constants
#define Bsz   32
#define Tn    512
#define Jn    25
#define DENC  256
#define Hn    512
#define G4    2048      // 4*H
#define NB    128       // persistent recurrence grid (co-resident)
#define NB2   64        // blocks per direction

// ---------------- scratch (device globals; no allocations) ----------------
__device__ float    g_enc [Bsz * Tn * DENC];
__device__ float    g_xg  [2L * Tn * Bsz * G4];           // [d][t][b][4H]
__device__ float    g_out0[Bsz * Tn * 2 * Hn];            // [b][t][2H]
__device__ float    g_out1[Bsz * Tn * 2 * Hn];
__device__ __align__(16) __half g_h[2][2 * Bsz * Hn];     // fp16 h, double-buffered
__device__ unsigned g_flag[2][NB2 * 32];                  // per-block flags, 128B apart

// ---------------- helpers --------------------------------------------------
__device__ __forceinline__ unsigned f2tf(float x) {
    unsigned u;
    asm("cvt.rna.tf32.f32 %0, %1;" : "=r"(u) : "f"(x));
    return u;
}

__device__ __forceinline__ void mma_tf32(float* c,
                                         unsigned a0, unsigned a1,
                                         unsigned a2, unsigned a3,
                                         unsigned b0, unsigned b1) {
    asm("mma.sync.aligned.m16n8k8.row.col.f32.tf32.tf32.f32 "
        "{%0,%1,%2,%3}, {%4,%5,%6,%7}, {%8,%9}, {%0,%1,%2,%3};"
        : "+f"(c[0]), "+f"(c[1]), "+f"(c[2]), "+f"(c[3])
        : "r"(a0), "r"(a1), "r"(a2), "r"(a3), "r"(b0), "r"(b1));
}

// ------------- contention-free per-direction grid barrier -----------------
// Each block STORES its own flag (no atomics -> no L2 ALU serialization).
// 64 threads poll the 64 peer flags in parallel (one L2 round-trip, MLP'd).
// target is monotonically increasing across the launch (wrap-safe compare).
__device__ __forceinline__ void flag_sync(int d, int myblk, unsigned target) {
    __threadfence();                 // h stores visible (gpu scope: CCTL.IVALL)
    __syncthreads();                 // all threads of this block stored h
    if (threadIdx.x == 0)
        *(volatile unsigned*)&g_flag[d][myblk * 32] = target;
    if (threadIdx.x < NB2) {
        volatile unsigned* f = &g_flag[d][threadIdx.x * 32];
        while ((int)(*f - target) < 0) { }
    }
    __syncthreads();
    __threadfence();                 // order subsequent h loads (L1 invalidate)
}

// ---------------- zero the output buffers ---------------------------------
__global__ void zero_kernel() {
    const int n4 = (Bsz * Tn * 2 * Hn) / 4;
    float4 z = make_float4(0.f, 0.f, 0.f, 0.f);
    for (int i = blockIdx.x * blockDim.x + threadIdx.x; i < n4;
         i += gridDim.x * blockDim.x) {
        reinterpret_cast<float4*>(g_out0)[i] = z;
        reinterpret_cast<float4*>(g_out1)[i] = z;
    }
}

// ---------------- encoder: relu(masked_xy @ W^T + b) ----------------------
__global__ void enc_kernel(const float* __restrict__ feats,
                           const float* __restrict__ W,
                           const float* __restrict__ bias) {
    __shared__ float xs[2 * Jn];
    const int bt  = blockIdx.x;
    const int tid = threadIdx.x;
    const float* f = feats + (size_t)bt * (Jn * 3);
    if (tid < Jn) {
        float c = (f[tid * 3 + 2] > 0.1f) ? 1.f : 0.f;
        xs[tid * 2 + 0] = f[tid * 3 + 0] * c;
        xs[tid * 2 + 1] = f[tid * 3 + 1] * c;
    }
    __syncthreads();
    const float* w = W + tid * (2 * Jn);
    float s = bias[tid];
#pragma unroll
    for (int k = 0; k < 2 * Jn; ++k) s += xs[k] * w[k];
    g_enc[(size_t)bt * DENC + tid] = fmaxf(s, 0.f);
}

// ---------------- input projection GEMM (tf32, double-buffered) -----------
// out_xg[d][t][b][g] = A[m=b*T+t,:K] . W[d][g,:K] + bias[d][g]
// block 128x128, 8 warps (2m x 4n), k-tile 16, ping-pong smem (1 sync/tile)
__global__ void __launch_bounds__(256)
proj_gemm(int srcSel, int K, const float* __restrict__ W,
          const float* __restrict__ bias) {
    const float* A  = srcSel ? g_out0 : g_enc;
    const int d  = blockIdx.z;
    const float* Wd = W + (size_t)d * G4 * K;
    const float* bd = bias + d * G4;
    const int n0 = blockIdx.x * 128;
    const int m0 = blockIdx.y * 128;

    __shared__ unsigned As[2][128 * 20];   // [m][k], stride 20 (conflict-free)
    __shared__ unsigned Ws[2][128 * 20];   // [n][k]

    const int tid  = threadIdx.x;
    const int lane = tid & 31;
    const int wid  = tid >> 5;
    const int wm   = (wid >> 2) * 64;
    const int wn   = (wid & 3) * 32;

    float acc[4][4][4];
#pragma unroll
    for (int mt = 0; mt < 4; ++mt)
#pragma unroll
        for (int nt = 0; nt < 4; ++nt)
#pragma unroll
            for (int i = 0; i < 4; ++i) acc[mt][nt][i] = 0.f;

    const int r0  = tid >> 2;
    const int kq0 = (tid & 3) << 2;

    float4 pa0, pa1, pw0, pw1;
    pa0 = *reinterpret_cast<const float4*>(A  + (size_t)(m0 + r0)      * K + kq0);
    pa1 = *reinterpret_cast<const float4*>(A  + (size_t)(m0 + r0 + 64) * K + kq0);
    pw0 = *reinterpret_cast<const float4*>(Wd + (size_t)(n0 + r0)      * K + kq0);
    pw1 = *reinterpret_cast<const float4*>(Wd + (size_t)(n0 + r0 + 64) * K + kq0);

    const int KT = K >> 4;
    for (int kt = 0; kt < KT; ++kt) {
        const int p = kt & 1;
        {
            uint4 u;
            u.x = f2tf(pa0.x); u.y = f2tf(pa0.y); u.z = f2tf(pa0.z); u.w = f2tf(pa0.w);
            *reinterpret_cast<uint4*>(As[p] + r0 * 20 + kq0) = u;
            u.x = f2tf(pa1.x); u.y = f2tf(pa1.y); u.z = f2tf(pa1.z); u.w = f2tf(pa1.w);
            *reinterpret_cast<uint4*>(As[p] + (r0 + 64) * 20 + kq0) = u;
            u.x = f2tf(pw0.x); u.y = f2tf(pw0.y); u.z = f2tf(pw0.z); u.w = f2tf(pw0.w);
            *reinterpret_cast<uint4*>(Ws[p] + r0 * 20 + kq0) = u;
            u.x = f2tf(pw1.x); u.y = f2tf(pw1.y); u.z = f2tf(pw1.z); u.w = f2tf(pw1.w);
            *reinterpret_cast<uint4*>(Ws[p] + (r0 + 64) * 20 + kq0) = u;
        }
        __syncthreads();     // single barrier per tile (ping-pong buffers)

        if (kt + 1 < KT) {   // prefetch next tile while computing
            int kn = (kt + 1) << 4;
            pa0 = *reinterpret_cast<const float4*>(A  + (size_t)(m0 + r0)      * K + kn + kq0);
            pa1 = *reinterpret_cast<const float4*>(A  + (size_t)(m0 + r0 + 64) * K + kn + kq0);
            pw0 = *reinterpret_cast<const float4*>(Wd + (size_t)(n0 + r0)      * K + kn + kq0);
            pw1 = *reinterpret_cast<const float4*>(Wd + (size_t)(n0 + r0 + 64) * K + kn + kq0);
        }

        const unsigned* Ab = As[p];
        const unsigned* Bb = Ws[p];
#pragma unroll
        for (int kk = 0; kk < 16; kk += 8) {
            unsigned af[4][4], bf[4][2];
#pragma unroll
            for (int mt = 0; mt < 4; ++mt) {
                const unsigned* pp = Ab + (wm + mt * 16 + (lane >> 2)) * 20 + kk + (lane & 3);
                af[mt][0] = pp[0];
                af[mt][1] = pp[8 * 20];
                af[mt][2] = pp[4];
                af[mt][3] = pp[8 * 20 + 4];
            }
#pragma unroll
            for (int nt = 0; nt < 4; ++nt) {
                const unsigned* pp = Bb + (wn + nt * 8 + (lane >> 2)) * 20 + kk + (lane & 3);
                bf[nt][0] = pp[0];
                bf[nt][1] = pp[4];
            }
#pragma unroll
            for (int mt = 0; mt < 4; ++mt)
#pragma unroll
                for (int nt = 0; nt < 4; ++nt)
                    mma_tf32(acc[mt][nt], af[mt][0], af[mt][1], af[mt][2], af[mt][3],
                             bf[nt][0], bf[nt][1]);
        }
    }

    // epilogue: bias + scatter to g_xg
#pragma unroll
    for (int mt = 0; mt < 4; ++mt) {
        int mrow0 = m0 + wm + mt * 16 + (lane >> 2);
#pragma unroll
        for (int nt = 0; nt < 4; ++nt) {
            int n = n0 + wn + nt * 8 + (lane & 3) * 2;
            float bv0 = bd[n], bv1 = bd[n + 1];
#pragma unroll
            for (int h = 0; h < 2; ++h) {
                int m  = mrow0 + h * 8;
                int t  = m & (Tn - 1);
                int bb = m >> 9;
                float* cp = g_xg + (((size_t)d * Tn + t) * Bsz + bb) * G4 + n;
                *reinterpret_cast<float2*>(cp) =
                    make_float2(acc[mt][nt][h * 2 + 0] + bv0,
                                acc[mt][nt][h * 2 + 1] + bv1);
            }
        }
    }
}

// ---------------- persistent bidirectional LSTM recurrence (tf32 MMA) -----
// R9 structure with the atomic grid barrier replaced by the contention-free
// per-block flag barrier (flag_sync). fp16 h transport kept.
#define REC_SMEM ((32 * 516 + 32 * 136) * 4)
extern __shared__ unsigned smr[];

__global__ void __launch_bounds__(256, 1)
rec_kernel(const float* __restrict__ whh,      // [2][4H][H]
           const int*   __restrict__ lengths,
           int outSel) {
    unsigned* hs   = smr;                          // [32 b][516] tf32 bits
    float*    part = (float*)(smr + 32 * 516);     // [32 b][136]
    float* out = outSel ? g_out1 : g_out0;
    const float* xg = g_xg;

    const int tid  = threadIdx.x;
    const int lane = tid & 31;
    const int wid  = tid >> 5;
    const int bx   = blockIdx.x;
    const int d    = bx >> 6;
    const int myblk = bx & 63;
    const int j0   = myblk << 3;
    const int mb   = wid & 1;             // batch half
    const int kc   = wid >> 1;            // K chunk (0..3), 128 k each

    // per-launch flag base: my own flag (only I write it); all flags are
    // uniform at launch entry, so every block computes the same base.
    __shared__ unsigned s_base;
    if (tid == 0) s_base = *(volatile unsigned*)&g_flag[d][myblk * 32];
    __syncthreads();
    const unsigned base = s_base;

    // stationary W fragments (B side): b0,b1 per (ks, nt=q)
    unsigned wb0[16][4], wb1[16][4];
    {
        const float* wdb = whh + (size_t)d * G4 * Hn;
#pragma unroll
        for (int ks = 0; ks < 16; ++ks)
#pragma unroll
            for (int nt = 0; nt < 4; ++nt) {
                const float* wp = wdb + (size_t)(nt * Hn + j0 + (lane >> 2)) * Hn
                                  + kc * 128 + ks * 8 + (lane & 3);
                wb0[ks][nt] = f2tf(wp[0]);
                wb1[ks][nt] = f2tf(wp[4]);
            }
    }

    // phase-2 identity: jj-major -> coalesced gmem
    const int jj = tid & 7;
    const int b2 = tid >> 3;              // 0..31
    const int len = lengths[b2];
    const int hidx = (d * Bsz + b2) * Hn + j0 + jj;
    float c_reg = 0.f;
    __half h_half = __float2half_rn(0.f);
    g_h[0][hidx] = h_half;

    flag_sync(d, myblk, base + 1);   // own dir's h buffer 0 zeroed

    for (int s = 0; s < Tn; ++s) {
        const int pr = s & 1, pw_ = pr ^ 1;
        const bool act = s < len;
        const int t = d ? (len - 1 - s) : s;

        // prefetch xg (32B-coalesced per (b,q) group)
        float xv0 = 0.f, xv1 = 0.f, xv2 = 0.f, xv3 = 0.f;
        if (act) {
            const float* xr = xg + (((size_t)d * Tn + t) * Bsz + b2) * G4 + j0 + jj;
            xv0 = xr[0];
            xv1 = xr[Hn];
            xv2 = xr[2 * Hn];
            xv3 = xr[3 * Hn];
        }

        // stage h (own dir, 32KB fp16) into smem as f32/tf32 bits
        {
            const __half* hsrc = g_h[pr] + d * Bsz * Hn;
#pragma unroll
            for (int i = 0; i < 8; ++i) {
                int f  = tid + i * 256;           // 0..2047 (8-half groups)
                int r  = f >> 6;                  // batch row 0..31
                int kq = (f & 63) << 3;           // k offset 0..504
                uint4 v = *reinterpret_cast<const uint4*>(hsrc + r * Hn + kq);
                const __half2* h2 = reinterpret_cast<const __half2*>(&v);
                float2 f0 = __half22float2(h2[0]);
                float2 f1 = __half22float2(h2[1]);
                float2 f2 = __half22float2(h2[2]);
                float2 f3 = __half22float2(h2[3]);
                uint4 o0, o1;
                o0.x = __float_as_uint(f0.x); o0.y = __float_as_uint(f0.y);
                o0.z = __float_as_uint(f1.x); o0.w = __float_as_uint(f1.y);
                o1.x = __float_as_uint(f2.x); o1.y = __float_as_uint(f2.y);
                o1.z = __float_as_uint(f3.x); o1.w = __float_as_uint(f3.y);
                *reinterpret_cast<uint4*>(hs + r * 516 + kq)     = o0;
                *reinterpret_cast<uint4*>(hs + r * 516 + kq + 4) = o1;
            }
        }
        __syncthreads();

        float acc[4][4];
#pragma unroll
        for (int nt = 0; nt < 4; ++nt)
#pragma unroll
            for (int i = 0; i < 4; ++i) acc[nt][i] = 0.f;

#pragma unroll
        for (int ks = 0; ks < 16; ++ks) {
            const unsigned* hp = hs + (mb * 16 + (lane >> 2)) * 516
                                 + kc * 128 + ks * 8 + (lane & 3);
            unsigned a0 = hp[0];
            unsigned a2 = hp[4];
            unsigned a1 = hp[8 * 516];
            unsigned a3 = hp[8 * 516 + 4];
#pragma unroll
            for (int nt = 0; nt < 4; ++nt)
                mma_tf32(acc[nt], a0, a1, a2, a3, wb0[ks][nt], wb1[ks][nt]);
        }

        // write K-chunk partials: part[batch][kc*32 + q*8 + jcol]
        {
            const int b_lo = mb * 16 + (lane >> 2);
            const int col  = kc * 32 + ((lane & 3) << 1);
#pragma unroll
            for (int nt = 0; nt < 4; ++nt) {
                float* pp = part + b_lo * 136 + col + nt * 8;
                *reinterpret_cast<float2*>(pp) =
                    make_float2(acc[nt][0], acc[nt][1]);
                *reinterpret_cast<float2*>(pp + 8 * 136) =
                    make_float2(acc[nt][2], acc[nt][3]);
            }
        }
        __syncthreads();

        // phase 2: reduce 4 K-chunk partials + gates (conflict-free reads)
        if (act) {
            const float* pb = part + b2 * 136 + jj;
            float gv[4];
#pragma unroll
            for (int q = 0; q < 4; ++q) {
                float v = (q == 0) ? xv0 : (q == 1) ? xv1 : (q == 2) ? xv2 : xv3;
#pragma unroll
                for (int k2 = 0; k2 < 4; ++k2)
                    v += pb[k2 * 32 + q * 8];
                gv[q] = v;
            }
            float ig = 1.f / (1.f + __expf(-gv[0]));
            float fg = 1.f / (1.f + __expf(-gv[1]));
            float gg = tanhf(gv[2]);
            float og = 1.f / (1.f + __expf(-gv[3]));
            c_reg = fg * c_reg + ig * gg;
            float hn = og * tanhf(c_reg);
            h_half = __float2half_rn(hn);
            out[((size_t)b2 * Tn + t) * (2 * Hn) + d * Hn + j0 + jj] = hn;
        }
        g_h[pw_][hidx] = h_half;   // frozen h re-written when inactive

        flag_sync(d, myblk, base + 2 + s);
    }
}

// ---------------- mean pooling over valid length --------------------------
__global__ void pool_kernel(const int* __restrict__ lengths,
                            float* __restrict__ out) {
    const int c = blockIdx.x * 256 + threadIdx.x;
    const int b = blockIdx.y;
    const float* p = g_out1 + (size_t)b * Tn * (2 * Hn) + c;
    float s = 0.f;
    for (int t = 0; t < Tn; ++t) s += p[(size_t)t * (2 * Hn)];
    out[b * (2 * Hn) + c] = s / (float)lengths[b];
}

// ---------------- launch ---------------------------------------------------
extern "C" void kernel_launch(void* const* d_in, const int* in_sizes, int n_in,
                              void* d_out, int out_size) {
    const float* feats = (const float*)d_in[0];
    const int*   lens  = (const int*)  d_in[1];
    const float* encW  = (const float*)d_in[2];
    const float* encb  = (const float*)d_in[3];
    const float* wih0  = (const float*)d_in[4];
    const float* whh0  = (const float*)d_in[5];
    const float* b0    = (const float*)d_in[6];
    const float* wih1  = (const float*)d_in[7];
    const float* whh1  = (const float*)d_in[8];
    const float* b1    = (const float*)d_in[9];
    float* out = (float*)d_out;

    // opt-in to >48KB dynamic smem (attribute set, not an allocation)
    cudaFuncSetAttribute(rec_kernel,
                         cudaFuncAttributeMaxDynamicSharedMemorySize, REC_SMEM);

    zero_kernel<<<2048, 256>>>();
    enc_kernel<<<Bsz * Tn, 256>>>(feats, encW, encb);

    // layer 0: project (K=256) then scan
    {
        dim3 grid(16, 128, 2);
        proj_gemm<<<grid, 256>>>(0, DENC, wih0, b0);
        rec_kernel<<<NB, 256, REC_SMEM>>>(whh0, lens, 0);
    }
    // layer 1: project (K=1024) then scan
    {
        dim3 grid(16, 128, 2);
        proj_gemm<<<grid, 256>>>(1, 2 * Hn, wih1, b1);
        rec_kernel<<<NB, 256, REC_SMEM>>>(whh1, lens, 1);
    }

    dim3 pg(4, Bsz);
    pool_kernel<<<pg, 256>>>(lens, out);
}

// round 12
// speedup vs baseline: 1.0779x; 1.0260x over previous
#include <cuda_runtime.h>
#include <math.h>

// Problem constants
#define Bsz   32
#define Tn    512
#define Jn    25
#define DENC  256
#define Hn    512
#define G4    2048      // 4*H
#define NB    128       // persistent recurrence grid (co-resident)
#define NB2   64        // blocks per direction

// ---------------- scratch (device globals; no allocations) ----------------
__device__ float    g_enc [Bsz * Tn * DENC];
__device__ float    g_xg  [2L * Tn * Bsz * G4];           // [d][t][b][4H]
__device__ float    g_out0[Bsz * Tn * 2 * Hn];            // [b][t][2H]
__device__ float    g_out1[Bsz * Tn * 2 * Hn];
__device__ __align__(16) unsigned g_h[2][2 * Bsz * Hn];   // tf32 bits, double-buffered
__device__ unsigned g_flag[2][NB2 * 32];                  // per-block flags, 128B apart

// ---------------- helpers --------------------------------------------------
__device__ __forceinline__ unsigned f2tf(float x) {
    unsigned u;
    asm("cvt.rna.tf32.f32 %0, %1;" : "=r"(u) : "f"(x));
    return u;
}

__device__ __forceinline__ void mma_tf32(float* c,
                                         unsigned a0, unsigned a1,
                                         unsigned a2, unsigned a3,
                                         unsigned b0, unsigned b1) {
    asm("mma.sync.aligned.m16n8k8.row.col.f32.tf32.tf32.f32 "
        "{%0,%1,%2,%3}, {%4,%5,%6,%7}, {%8,%9}, {%0,%1,%2,%3};"
        : "+f"(c[0]), "+f"(c[1]), "+f"(c[2]), "+f"(c[3])
        : "r"(a0), "r"(a1), "r"(a2), "r"(a3), "r"(b0), "r"(b1));
}

__device__ __forceinline__ void st_release_gpu(unsigned* p, unsigned v) {
    asm volatile("st.release.gpu.global.u32 [%0], %1;" :: "l"(p), "r"(v) : "memory");
}
__device__ __forceinline__ unsigned ld_acquire_gpu(const unsigned* p) {
    unsigned v;
    asm volatile("ld.acquire.gpu.global.u32 %0, [%1];" : "=r"(v) : "l"(p) : "memory");
    return v;
}
__device__ __forceinline__ void cp_async16(unsigned smem_word_addr_bytes,
                                           const void* gptr) {
    asm volatile("cp.async.cg.shared.global [%0], [%1], 16;"
                 :: "r"(smem_word_addr_bytes), "l"(gptr));
}

// ------------- contention-free per-direction grid barrier -----------------
// Producer: release-store OWN flag (orders this block's prior h stores via
// the __syncthreads happens-before edge). Consumers: 64 parallel acquire-load
// polls (one L2 round-trip, MLP'd). No MEMBAR.GPU, no L1 flush.
__device__ __forceinline__ void flag_sync(int d, int myblk, unsigned target) {
    __syncthreads();                 // all threads of this block stored h
    if (threadIdx.x == 0)
        st_release_gpu(&g_flag[d][myblk * 32], target);
    if (threadIdx.x < NB2) {
        unsigned* f = &g_flag[d][threadIdx.x * 32];
        while ((int)(ld_acquire_gpu(f) - target) < 0) { }
    }
    __syncthreads();
}

// ---------------- zero the output buffers ---------------------------------
__global__ void zero_kernel() {
    const int n4 = (Bsz * Tn * 2 * Hn) / 4;
    float4 z = make_float4(0.f, 0.f, 0.f, 0.f);
    for (int i = blockIdx.x * blockDim.x + threadIdx.x; i < n4;
         i += gridDim.x * blockDim.x) {
        reinterpret_cast<float4*>(g_out0)[i] = z;
        reinterpret_cast<float4*>(g_out1)[i] = z;
    }
}

// ---------------- encoder: relu(masked_xy @ W^T + b) ----------------------
__global__ void enc_kernel(const float* __restrict__ feats,
                           const float* __restrict__ W,
                           const float* __restrict__ bias) {
    __shared__ float xs[2 * Jn];
    const int bt  = blockIdx.x;
    const int tid = threadIdx.x;
    const float* f = feats + (size_t)bt * (Jn * 3);
    if (tid < Jn) {
        float c = (f[tid * 3 + 2] > 0.1f) ? 1.f : 0.f;
        xs[tid * 2 + 0] = f[tid * 3 + 0] * c;
        xs[tid * 2 + 1] = f[tid * 3 + 1] * c;
    }
    __syncthreads();
    const float* w = W + tid * (2 * Jn);
    float s = bias[tid];
#pragma unroll
    for (int k = 0; k < 2 * Jn; ++k) s += xs[k] * w[k];
    g_enc[(size_t)bt * DENC + tid] = fmaxf(s, 0.f);
}

// ---------------- input projection GEMM (tf32, double-buffered) -----------
// out_xg[d][t][b][g] = A[m=b*T+t,:K] . W[d][g,:K] + bias[d][g]
// block 128x128, 8 warps (2m x 4n), k-tile 16, ping-pong smem (1 sync/tile)
__global__ void __launch_bounds__(256)
proj_gemm(int srcSel, int K, const float* __restrict__ W,
          const float* __restrict__ bias) {
    const float* A  = srcSel ? g_out0 : g_enc;
    const int d  = blockIdx.z;
    const float* Wd = W + (size_t)d * G4 * K;
    const float* bd = bias + d * G4;
    const int n0 = blockIdx.x * 128;
    const int m0 = blockIdx.y * 128;

    __shared__ unsigned As[2][128 * 20];   // [m][k], stride 20 (conflict-free)
    __shared__ unsigned Ws[2][128 * 20];   // [n][k]

    const int tid  = threadIdx.x;
    const int lane = tid & 31;
    const int wid  = tid >> 5;
    const int wm   = (wid >> 2) * 64;
    const int wn   = (wid & 3) * 32;

    float acc[4][4][4];
#pragma unroll
    for (int mt = 0; mt < 4; ++mt)
#pragma unroll
        for (int nt = 0; nt < 4; ++nt)
#pragma unroll
            for (int i = 0; i < 4; ++i) acc[mt][nt][i] = 0.f;

    const int r0  = tid >> 2;
    const int kq0 = (tid & 3) << 2;

    float4 pa0, pa1, pw0, pw1;
    pa0 = *reinterpret_cast<const float4*>(A  + (size_t)(m0 + r0)      * K + kq0);
    pa1 = *reinterpret_cast<const float4*>(A  + (size_t)(m0 + r0 + 64) * K + kq0);
    pw0 = *reinterpret_cast<const float4*>(Wd + (size_t)(n0 + r0)      * K + kq0);
    pw1 = *reinterpret_cast<const float4*>(Wd + (size_t)(n0 + r0 + 64) * K + kq0);

    const int KT = K >> 4;
    for (int kt = 0; kt < KT; ++kt) {
        const int p = kt & 1;
        {
            uint4 u;
            u.x = f2tf(pa0.x); u.y = f2tf(pa0.y); u.z = f2tf(pa0.z); u.w = f2tf(pa0.w);
            *reinterpret_cast<uint4*>(As[p] + r0 * 20 + kq0) = u;
            u.x = f2tf(pa1.x); u.y = f2tf(pa1.y); u.z = f2tf(pa1.z); u.w = f2tf(pa1.w);
            *reinterpret_cast<uint4*>(As[p] + (r0 + 64) * 20 + kq0) = u;
            u.x = f2tf(pw0.x); u.y = f2tf(pw0.y); u.z = f2tf(pw0.z); u.w = f2tf(pw0.w);
            *reinterpret_cast<uint4*>(Ws[p] + r0 * 20 + kq0) = u;
            u.x = f2tf(pw1.x); u.y = f2tf(pw1.y); u.z = f2tf(pw1.z); u.w = f2tf(pw1.w);
            *reinterpret_cast<uint4*>(Ws[p] + (r0 + 64) * 20 + kq0) = u;
        }
        __syncthreads();     // single barrier per tile (ping-pong buffers)

        if (kt + 1 < KT) {   // prefetch next tile while computing
            int kn = (kt + 1) << 4;
            pa0 = *reinterpret_cast<const float4*>(A  + (size_t)(m0 + r0)      * K + kn + kq0);
            pa1 = *reinterpret_cast<const float4*>(A  + (size_t)(m0 + r0 + 64) * K + kn + kq0);
            pw0 = *reinterpret_cast<const float4*>(Wd + (size_t)(n0 + r0)      * K + kn + kq0);
            pw1 = *reinterpret_cast<const float4*>(Wd + (size_t)(n0 + r0 + 64) * K + kn + kq0);
        }

        const unsigned* Ab = As[p];
        const unsigned* Bb = Ws[p];
#pragma unroll
        for (int kk = 0; kk < 16; kk += 8) {
            unsigned af[4][4], bf[4][2];
#pragma unroll
            for (int mt = 0; mt < 4; ++mt) {
                const unsigned* pp = Ab + (wm + mt * 16 + (lane >> 2)) * 20 + kk + (lane & 3);
                af[mt][0] = pp[0];
                af[mt][1] = pp[8 * 20];
                af[mt][2] = pp[4];
                af[mt][3] = pp[8 * 20 + 4];
            }
#pragma unroll
            for (int nt = 0; nt < 4; ++nt) {
                const unsigned* pp = Bb + (wn + nt * 8 + (lane >> 2)) * 20 + kk + (lane & 3);
                bf[nt][0] = pp[0];
                bf[nt][1] = pp[4];
            }
#pragma unroll
            for (int mt = 0; mt < 4; ++mt)
#pragma unroll
                for (int nt = 0; nt < 4; ++nt)
                    mma_tf32(acc[mt][nt], af[mt][0], af[mt][1], af[mt][2], af[mt][3],
                             bf[nt][0], bf[nt][1]);
        }
    }

    // epilogue: bias + scatter to g_xg
#pragma unroll
    for (int mt = 0; mt < 4; ++mt) {
        int mrow0 = m0 + wm + mt * 16 + (lane >> 2);
#pragma unroll
        for (int nt = 0; nt < 4; ++nt) {
            int n = n0 + wn + nt * 8 + (lane & 3) * 2;
            float bv0 = bd[n], bv1 = bd[n + 1];
#pragma unroll
            for (int h = 0; h < 2; ++h) {
                int m  = mrow0 + h * 8;
                int t  = m & (Tn - 1);
                int bb = m >> 9;
                float* cp = g_xg + (((size_t)d * Tn + t) * Bsz + bb) * G4 + n;
                *reinterpret_cast<float2*>(cp) =
                    make_float2(acc[mt][nt][h * 2 + 0] + bv0,
                                acc[mt][nt][h * 2 + 1] + bv1);
            }
        }
    }
}

// ---------------- persistent bidirectional LSTM recurrence (tf32 MMA) -----
// R10 structure, latency-chain slimmed:
//  - h transported as tf32 bits; staging via cp.async.cg (L1-bypass, no
//    register round-trip, no conversions)
//  - release/acquire flag barrier (no MEMBAR.GPU, no CCTL.IVALL)
//  - step loop trimmed to max(lengths)
#define REC_SMEM ((32 * 516 + 32 * 136) * 4)
extern __shared__ unsigned smr[];

__global__ void __launch_bounds__(256, 1)
rec_kernel(const float* __restrict__ whh,      // [2][4H][H]
           const int*   __restrict__ lengths,
           int outSel) {
    unsigned* hs   = smr;                          // [32 b][516] tf32 bits
    float*    part = (float*)(smr + 32 * 516);     // [32 b][136]
    float* out = outSel ? g_out1 : g_out0;
    const float* xg = g_xg;

    const int tid  = threadIdx.x;
    const int lane = tid & 31;
    const int wid  = tid >> 5;
    const int bx   = blockIdx.x;
    const int d    = bx >> 6;
    const int myblk = bx & 63;
    const int j0   = myblk << 3;
    const int mb   = wid & 1;             // batch half
    const int kc   = wid >> 1;            // K chunk (0..3), 128 k each

    // per-launch flag base + max length (uniform across all blocks)
    __shared__ unsigned s_base;
    __shared__ int s_maxlen;
    if (wid == 0) {
        int L = lengths[lane];
#pragma unroll
        for (int off = 16; off > 0; off >>= 1)
            L = max(L, __shfl_xor_sync(0xffffffffu, L, off));
        if (lane == 0) {
            s_maxlen = L;
            s_base = *(volatile unsigned*)&g_flag[d][myblk * 32];
        }
    }

    // stationary W fragments (B side): b0,b1 per (ks, nt=q)
    unsigned wb0[16][4], wb1[16][4];
    {
        const float* wdb = whh + (size_t)d * G4 * Hn;
#pragma unroll
        for (int ks = 0; ks < 16; ++ks)
#pragma unroll
            for (int nt = 0; nt < 4; ++nt) {
                const float* wp = wdb + (size_t)(nt * Hn + j0 + (lane >> 2)) * Hn
                                  + kc * 128 + ks * 8 + (lane & 3);
                wb0[ks][nt] = f2tf(wp[0]);
                wb1[ks][nt] = f2tf(wp[4]);
            }
    }

    // phase-2 identity: jj-major -> coalesced gmem
    const int jj = tid & 7;
    const int b2 = tid >> 3;              // 0..31
    const int len = lengths[b2];
    const int hidx = (d * Bsz + b2) * Hn + j0 + jj;
    float c_reg = 0.f;
    unsigned h_bits = 0u;
    g_h[0][hidx] = 0u;

    __syncthreads();
    const unsigned base = s_base;
    const int smax = s_maxlen;

    flag_sync(d, myblk, base + 1);   // own dir's h buffer 0 zeroed

    const unsigned hs_smem_base = (unsigned)__cvta_generic_to_shared(hs);

    for (int s = 0; s < smax; ++s) {
        const int pr = s & 1, pw_ = pr ^ 1;
        const bool act = s < len;
        const int t = d ? (len - 1 - s) : s;

        // prefetch xg (32B-coalesced per (b,q) group)
        float xv0 = 0.f, xv1 = 0.f, xv2 = 0.f, xv3 = 0.f;
        if (act) {
            const float* xr = xg + (((size_t)d * Tn + t) * Bsz + b2) * G4 + j0 + jj;
            xv0 = xr[0];
            xv1 = xr[Hn];
            xv2 = xr[2 * Hn];
            xv3 = xr[3 * Hn];
        }

        // stage h (own dir, 64KB tf32 bits) smem via cp.async.cg (L1 bypass)
        {
            const unsigned* hsrc = g_h[pr] + d * Bsz * Hn;
#pragma unroll
            for (int i = 0; i < 16; ++i) {
                int f = tid + i * 256;            // uint4 index, 0..4095
                int r = f >> 7, kq = (f & 127) << 2;
                cp_async16(hs_smem_base + (r * 516 + kq) * 4,
                           hsrc + r * Hn + kq);
            }
            asm volatile("cp.async.commit_group;" ::: "memory");
            asm volatile("cp.async.wait_group 0;" ::: "memory");
        }
        __syncthreads();

        float acc[4][4];
#pragma unroll
        for (int nt = 0; nt < 4; ++nt)
#pragma unroll
            for (int i = 0; i < 4; ++i) acc[nt][i] = 0.f;

#pragma unroll
        for (int ks = 0; ks < 16; ++ks) {
            const unsigned* hp = hs + (mb * 16 + (lane >> 2)) * 516
                                 + kc * 128 + ks * 8 + (lane & 3);
            unsigned a0 = hp[0];
            unsigned a2 = hp[4];
            unsigned a1 = hp[8 * 516];
            unsigned a3 = hp[8 * 516 + 4];
#pragma unroll
            for (int nt = 0; nt < 4; ++nt)
                mma_tf32(acc[nt], a0, a1, a2, a3, wb0[ks][nt], wb1[ks][nt]);
        }

        // write K-chunk partials: part[batch][kc*32 + q*8 + jcol]
        {
            const int b_lo = mb * 16 + (lane >> 2);
            const int col  = kc * 32 + ((lane & 3) << 1);
#pragma unroll
            for (int nt = 0; nt < 4; ++nt) {
                float* pp = part + b_lo * 136 + col + nt * 8;
                *reinterpret_cast<float2*>(pp) =
                    make_float2(acc[nt][0], acc[nt][1]);
                *reinterpret_cast<float2*>(pp + 8 * 136) =
                    make_float2(acc[nt][2], acc[nt][3]);
            }
        }
        __syncthreads();

        // phase 2: reduce 4 K-chunk partials + gates (conflict-free reads)
        if (act) {
            const float* pb = part + b2 * 136 + jj;
            float gv[4];
#pragma unroll
            for (int q = 0; q < 4; ++q) {
                float v = (q == 0) ? xv0 : (q == 1) ? xv1 : (q == 2) ? xv2 : xv3;
#pragma unroll
                for (int k2 = 0; k2 < 4; ++k2)
                    v += pb[k2 * 32 + q * 8];
                gv[q] = v;
            }
            float ig = 1.f / (1.f + __expf(-gv[0]));
            float fg = 1.f / (1.f + __expf(-gv[1]));
            float gg = tanhf(gv[2]);
            float og = 1.f / (1.f + __expf(-gv[3]));
            c_reg = fg * c_reg + ig * gg;
            float hn = og * tanhf(c_reg);
            h_bits = f2tf(hn);
            out[((size_t)b2 * Tn + t) * (2 * Hn) + d * Hn + j0 + jj] = hn;
        }
        g_h[pw_][hidx] = h_bits;   // frozen h re-written when inactive

        flag_sync(d, myblk, base + 2 + s);
    }
}

// ---------------- mean pooling over valid length --------------------------
__global__ void pool_kernel(const int* __restrict__ lengths,
                            float* __restrict__ out) {
    const int c = blockIdx.x * 256 + threadIdx.x;
    const int b = blockIdx.y;
    const float* p = g_out1 + (size_t)b * Tn * (2 * Hn) + c;
    float s = 0.f;
    for (int t = 0; t < Tn; ++t) s += p[(size_t)t * (2 * Hn)];
    out[b * (2 * Hn) + c] = s / (float)lengths[b];
}

// ---------------- launch ---------------------------------------------------
extern "C" void kernel_launch(void* const* d_in, const int* in_sizes, int n_in,
                              void* d_out, int out_size) {
    const float* feats = (const float*)d_in[0];
    const int*   lens  = (const int*)  d_in[1];
    const float* encW  = (const float*)d_in[2];
    const float* encb  = (const float*)d_in[3];
    const float* wih0  = (const float*)d_in[4];
    const float* whh0  = (const float*)d_in[5];
    const float* b0    = (const float*)d_in[6];
    const float* wih1  = (const float*)d_in[7];
    const float* whh1  = (const float*)d_in[8];
    const float* b1    = (const float*)d_in[9];
    float* out = (float*)d_out;

    // opt-in to >48KB dynamic smem (attribute set, not an allocation)
    cudaFuncSetAttribute(rec_kernel,
                         cudaFuncAttributeMaxDynamicSharedMemorySize, REC_SMEM);

    zero_kernel<<<2048, 256>>>();
    enc_kernel<<<Bsz * Tn, 256>>>(feats, encW, encb);

    // layer 0: project (K=256) then scan
    {
        dim3 grid(16, 128, 2);
        proj_gemm<<<grid, 256>>>(0, DENC, wih0, b0);
        rec_kernel<<<NB, 256, REC_SMEM>>>(whh0, lens, 0);
    }
    // layer 1: project (K=1024) then scan
    {
        dim3 grid(16, 128, 2);
        proj_gemm<<<grid, 256>>>(1, 2 * Hn, wih1, b1);
        rec_kernel<<<NB, 256, REC_SMEM>>>(whh1, lens, 1);
    }

    dim3 pg(4, Bsz);
    pool_kernel<<<pg, 256>>>(lens, out);
}

// round 13
// speedup vs baseline: 1.1209x; 1.0399x over previous
#include <cuda_runtime.h>
#include <math.h>

// Problem constants
#define Bsz   32
#define Tn    512
#define Jn    25
#define DENC  256
#define Hn    512
#define G4    2048      // 4*H
#define NB    128       // persistent recurrence grid (co-resident)
#define NB2   64        // blocks per direction

// ---------------- scratch (device globals; no allocations) ----------------
__device__ float    g_enc [Bsz * Tn * DENC];
__device__ float    g_xg  [2L * Tn * Bsz * G4];           // [d][t][b][4H]
__device__ float    g_out0[Bsz * Tn * 2 * Hn];            // [b][t][2H]
__device__ float    g_out1[Bsz * Tn * 2 * Hn];
__device__ __align__(16) unsigned g_h[2][2 * Bsz * Hn];   // tf32 bits, double-buffered
__device__ unsigned g_flag[2][NB2 * 32];                  // per-block flags, 128B apart

// ---------------- helpers --------------------------------------------------
__device__ __forceinline__ unsigned f2tf(float x) {
    unsigned u;
    asm("cvt.rna.tf32.f32 %0, %1;" : "=r"(u) : "f"(x));
    return u;
}

__device__ __forceinline__ void mma_tf32(float* c,
                                         unsigned a0, unsigned a1,
                                         unsigned a2, unsigned a3,
                                         unsigned b0, unsigned b1) {
    asm("mma.sync.aligned.m16n8k8.row.col.f32.tf32.tf32.f32 "
        "{%0,%1,%2,%3}, {%4,%5,%6,%7}, {%8,%9}, {%0,%1,%2,%3};"
        : "+f"(c[0]), "+f"(c[1]), "+f"(c[2]), "+f"(c[3])
        : "r"(a0), "r"(a1), "r"(a2), "r"(a3), "r"(b0), "r"(b1));
}

__device__ __forceinline__ void st_release_gpu(unsigned* p, unsigned v) {
    asm volatile("st.release.gpu.global.u32 [%0], %1;" :: "l"(p), "r"(v) : "memory");
}
__device__ __forceinline__ unsigned ld_acquire_gpu(const unsigned* p) {
    unsigned v;
    asm volatile("ld.acquire.gpu.global.u32 %0, [%1];" : "=r"(v) : "l"(p) : "memory");
    return v;
}
__device__ __forceinline__ void cp_async16(unsigned smem_addr_bytes,
                                           const void* gptr) {
    asm volatile("cp.async.cg.shared.global [%0], [%1], 16;"
                 :: "r"(smem_addr_bytes), "l"(gptr));
}

// ------------- contention-free per-direction grid barrier -----------------
__device__ __forceinline__ void flag_sync(int d, int myblk, unsigned target) {
    __syncthreads();                 // all threads of this block stored h
    if (threadIdx.x == 0)
        st_release_gpu(&g_flag[d][myblk * 32], target);
    if (threadIdx.x < NB2) {
        unsigned* f = &g_flag[d][threadIdx.x * 32];
        while ((int)(ld_acquire_gpu(f) - target) < 0) { }
    }
    __syncthreads();
}

// ---------------- zero the output buffers ---------------------------------
__global__ void zero_kernel() {
    const int n4 = (Bsz * Tn * 2 * Hn) / 4;
    float4 z = make_float4(0.f, 0.f, 0.f, 0.f);
    for (int i = blockIdx.x * blockDim.x + threadIdx.x; i < n4;
         i += gridDim.x * blockDim.x) {
        reinterpret_cast<float4*>(g_out0)[i] = z;
        reinterpret_cast<float4*>(g_out1)[i] = z;
    }
}

// ---------------- encoder: relu(masked_xy @ W^T + b) ----------------------
__global__ void enc_kernel(const float* __restrict__ feats,
                           const float* __restrict__ W,
                           const float* __restrict__ bias) {
    __shared__ float xs[2 * Jn];
    const int bt  = blockIdx.x;
    const int tid = threadIdx.x;
    const float* f = feats + (size_t)bt * (Jn * 3);
    if (tid < Jn) {
        float c = (f[tid * 3 + 2] > 0.1f) ? 1.f : 0.f;
        xs[tid * 2 + 0] = f[tid * 3 + 0] * c;
        xs[tid * 2 + 1] = f[tid * 3 + 1] * c;
    }
    __syncthreads();
    const float* w = W + tid * (2 * Jn);
    float s = bias[tid];
#pragma unroll
    for (int k = 0; k < 2 * Jn; ++k) s += xs[k] * w[k];
    g_enc[(size_t)bt * DENC + tid] = fmaxf(s, 0.f);
}

// ---------------- input projection GEMM (tf32, k-tile 32 ping-pong) -------
// out_xg[d][t][b][g] = A[m=b*T+t,:K] . W[d][g,:K] + bias[d][g]
// block 128x128, 8 warps (2m x 4n), k-tile 32, 1 sync per tile
#define PROJ_SMEM (4 * 128 * 36 * 4)
extern __shared__ unsigned smp[];

__global__ void __launch_bounds__(256)
proj_gemm(int srcSel, int K, const float* __restrict__ W,
          const float* __restrict__ bias) {
    const float* A  = srcSel ? g_out0 : g_enc;
    const int d  = blockIdx.z;
    const float* Wd = W + (size_t)d * G4 * K;
    const float* bd = bias + d * G4;
    const int n0 = blockIdx.x * 128;
    const int m0 = blockIdx.y * 128;

    unsigned* As = smp;                   // [2][128*36]
    unsigned* Bs = smp + 2 * 128 * 36;

    const int tid  = threadIdx.x;
    const int lane = tid & 31;
    const int wid  = tid >> 5;
    const int wm   = (wid >> 2) * 64;
    const int wn   = (wid & 3) * 32;

    float acc[4][4][4];
#pragma unroll
    for (int mt = 0; mt < 4; ++mt)
#pragma unroll
        for (int nt = 0; nt < 4; ++nt)
#pragma unroll
            for (int i = 0; i < 4; ++i) acc[mt][nt][i] = 0.f;

    float4 ra[4], rw[4];
#pragma unroll
    for (int j = 0; j < 4; ++j) {
        int u = tid + j * 256, r = u >> 3, kq = (u & 7) << 2;
        ra[j] = *reinterpret_cast<const float4*>(A  + (size_t)(m0 + r) * K + kq);
        rw[j] = *reinterpret_cast<const float4*>(Wd + (size_t)(n0 + r) * K + kq);
    }

    const int KT = K >> 5;
    for (int kt = 0; kt < KT; ++kt) {
        const int p = kt & 1;
#pragma unroll
        for (int j = 0; j < 4; ++j) {
            int u = tid + j * 256, r = u >> 3, kq = (u & 7) << 2;
            uint4 ua, uw;
            ua.x = f2tf(ra[j].x); ua.y = f2tf(ra[j].y);
            ua.z = f2tf(ra[j].z); ua.w = f2tf(ra[j].w);
            uw.x = f2tf(rw[j].x); uw.y = f2tf(rw[j].y);
            uw.z = f2tf(rw[j].z); uw.w = f2tf(rw[j].w);
            *reinterpret_cast<uint4*>(As + p * 4608 + r * 36 + kq) = ua;
            *reinterpret_cast<uint4*>(Bs + p * 4608 + r * 36 + kq) = uw;
        }
        __syncthreads();     // single barrier per k-tile (ping-pong)

        if (kt + 1 < KT) {   // prefetch next tile while computing
            int kb = (kt + 1) * 32;
#pragma unroll
            for (int j = 0; j < 4; ++j) {
                int u = tid + j * 256, r = u >> 3, kq = (u & 7) << 2;
                ra[j] = *reinterpret_cast<const float4*>(A  + (size_t)(m0 + r) * K + kb + kq);
                rw[j] = *reinterpret_cast<const float4*>(Wd + (size_t)(n0 + r) * K + kb + kq);
            }
        }

        const unsigned* Ab = As + p * 4608;
        const unsigned* Bb = Bs + p * 4608;
#pragma unroll
        for (int kk = 0; kk < 32; kk += 8) {
            unsigned af[4][4], bf[4][2];
#pragma unroll
            for (int mt = 0; mt < 4; ++mt) {
                const unsigned* pp = Ab + (wm + mt * 16 + (lane >> 2)) * 36 + kk + (lane & 3);
                af[mt][0] = pp[0];
                af[mt][1] = pp[8 * 36];
                af[mt][2] = pp[4];
                af[mt][3] = pp[8 * 36 + 4];
            }
#pragma unroll
            for (int nt = 0; nt < 4; ++nt) {
                const unsigned* pp = Bb + (wn + nt * 8 + (lane >> 2)) * 36 + kk + (lane & 3);
                bf[nt][0] = pp[0];
                bf[nt][1] = pp[4];
            }
#pragma unroll
            for (int mt = 0; mt < 4; ++mt)
#pragma unroll
                for (int nt = 0; nt < 4; ++nt)
                    mma_tf32(acc[mt][nt], af[mt][0], af[mt][1], af[mt][2], af[mt][3],
                             bf[nt][0], bf[nt][1]);
        }
        __syncthreads();
    }

    // epilogue: bias + scatter to g_xg
#pragma unroll
    for (int mt = 0; mt < 4; ++mt) {
        int mrow0 = m0 + wm + mt * 16 + (lane >> 2);
#pragma unroll
        for (int nt = 0; nt < 4; ++nt) {
            int n = n0 + wn + nt * 8 + (lane & 3) * 2;
            float bv0 = bd[n], bv1 = bd[n + 1];
#pragma unroll
            for (int h = 0; h < 2; ++h) {
                int m  = mrow0 + h * 8;
                int t  = m & (Tn - 1);
                int bb = m >> 9;
                float* cp = g_xg + (((size_t)d * Tn + t) * Bsz + bb) * G4 + n;
                *reinterpret_cast<float2*>(cp) =
                    make_float2(acc[mt][nt][h * 2 + 0] + bv0,
                                acc[mt][nt][h * 2 + 1] + bv1);
            }
        }
    }
}

// ---------------- persistent bidirectional LSTM recurrence (tf32 MMA) -----
// R11 + per-warp private h staging: each warp cp.asyncs ONLY its own
// (mb,kc) fragment region -> no block-wide staging barrier, no cross-warp
// staging skew on the critical chain.
#define REC_SMEM ((32 * 516 + 32 * 136) * 4)
extern __shared__ unsigned smr[];

__global__ void __launch_bounds__(256, 1)
rec_kernel(const float* __restrict__ whh,      // [2][4H][H]
           const int*   __restrict__ lengths,
           int outSel) {
    unsigned* hs   = smr;                          // [32 b][516] tf32 bits
    float*    part = (float*)(smr + 32 * 516);     // [32 b][136]
    float* out = outSel ? g_out1 : g_out0;
    const float* xg = g_xg;

    const int tid  = threadIdx.x;
    const int lane = tid & 31;
    const int wid  = tid >> 5;
    const int bx   = blockIdx.x;
    const int d    = bx >> 6;
    const int myblk = bx & 63;
    const int j0   = myblk << 3;
    const int mb   = wid & 1;             // batch half
    const int kc   = wid >> 1;            // K chunk (0..3), 128 k each

    // per-launch flag base + max length (uniform across all blocks)
    __shared__ unsigned s_base;
    __shared__ int s_maxlen;
    if (wid == 0) {
        int L = lengths[lane];
#pragma unroll
        for (int off = 16; off > 0; off >>= 1)
            L = max(L, __shfl_xor_sync(0xffffffffu, L, off));
        if (lane == 0) {
            s_maxlen = L;
            s_base = *(volatile unsigned*)&g_flag[d][myblk * 32];
        }
    }

    // stationary W fragments (B side): b0,b1 per (ks, nt=q)
    unsigned wb0[16][4], wb1[16][4];
    {
        const float* wdb = whh + (size_t)d * G4 * Hn;
#pragma unroll
        for (int ks = 0; ks < 16; ++ks)
#pragma unroll
            for (int nt = 0; nt < 4; ++nt) {
                const float* wp = wdb + (size_t)(nt * Hn + j0 + (lane >> 2)) * Hn
                                  + kc * 128 + ks * 8 + (lane & 3);
                wb0[ks][nt] = f2tf(wp[0]);
                wb1[ks][nt] = f2tf(wp[4]);
            }
    }

    // phase-2 identity: jj-major -> coalesced gmem
    const int jj = tid & 7;
    const int b2 = tid >> 3;              // 0..31
    const int len = lengths[b2];
    const int hidx = (d * Bsz + b2) * Hn + j0 + jj;
    float c_reg = 0.f;
    unsigned h_bits = 0u;
    g_h[0][hidx] = 0u;

    __syncthreads();
    const unsigned base = s_base;
    const int smax = s_maxlen;

    flag_sync(d, myblk, base + 1);   // own dir's h buffer 0 zeroed

    // warp-private staging geometry: rows mb*16..+15, cols kc*128..+127
    const unsigned hs_warp_smem = (unsigned)__cvta_generic_to_shared(hs)
                                  + ((mb * 16) * 516 + kc * 128) * 4;
    const int h_warp_goff = (d * Bsz + mb * 16) * Hn + kc * 128;

    for (int s = 0; s < smax; ++s) {
        const int pr = s & 1, pw_ = pr ^ 1;
        const bool act = s < len;
        const int t = d ? (len - 1 - s) : s;

        // prefetch xg (32B-coalesced per (b,q) group)
        float xv0 = 0.f, xv1 = 0.f, xv2 = 0.f, xv3 = 0.f;
        if (act) {
            const float* xr = xg + (((size_t)d * Tn + t) * Bsz + b2) * G4 + j0 + jj;
            xv0 = xr[0];
            xv1 = xr[Hn];
            xv2 = xr[2 * Hn];
            xv3 = xr[3 * Hn];
        }

        // stage OWN fragment region only (8KB/warp, no block barrier)
        {
            const unsigned* hsrc = g_h[pr] + h_warp_goff;
#pragma unroll
            for (int i = 0; i < 16; ++i)
                cp_async16(hs_warp_smem + (i * 516 + lane * 4) * 4,
                           hsrc + i * Hn + lane * 4);
            asm volatile("cp.async.commit_group;" ::: "memory");
            asm volatile("cp.async.wait_group 0;" ::: "memory");
            __syncwarp();
        }

        float acc[4][4];
#pragma unroll
        for (int nt = 0; nt < 4; ++nt)
#pragma unroll
            for (int i = 0; i < 4; ++i) acc[nt][i] = 0.f;

#pragma unroll
        for (int ks = 0; ks < 16; ++ks) {
            const unsigned* hp = hs + (mb * 16 + (lane >> 2)) * 516
                                 + kc * 128 + ks * 8 + (lane & 3);
            unsigned a0 = hp[0];
            unsigned a2 = hp[4];
            unsigned a1 = hp[8 * 516];
            unsigned a3 = hp[8 * 516 + 4];
#pragma unroll
            for (int nt = 0; nt < 4; ++nt)
                mma_tf32(acc[nt], a0, a1, a2, a3, wb0[ks][nt], wb1[ks][nt]);
        }

        // write K-chunk partials: part[batch][kc*32 + q*8 + jcol]
        {
            const int b_lo = mb * 16 + (lane >> 2);
            const int col  = kc * 32 + ((lane & 3) << 1);
#pragma unroll
            for (int nt = 0; nt < 4; ++nt) {
                float* pp = part + b_lo * 136 + col + nt * 8;
                *reinterpret_cast<float2*>(pp) =
                    make_float2(acc[nt][0], acc[nt][1]);
                *reinterpret_cast<float2*>(pp + 8 * 136) =
                    make_float2(acc[nt][2], acc[nt][3]);
            }
        }
        __syncthreads();

        // phase 2: reduce 4 K-chunk partials + gates (conflict-free reads)
        if (act) {
            const float* pb = part + b2 * 136 + jj;
            float gv[4];
#pragma unroll
            for (int q = 0; q < 4; ++q) {
                float v = (q == 0) ? xv0 : (q == 1) ? xv1 : (q == 2) ? xv2 : xv3;
#pragma unroll
                for (int k2 = 0; k2 < 4; ++k2)
                    v += pb[k2 * 32 + q * 8];
                gv[q] = v;
            }
            float ig = 1.f / (1.f + __expf(-gv[0]));
            float fg = 1.f / (1.f + __expf(-gv[1]));
            float gg = tanhf(gv[2]);
            float og = 1.f / (1.f + __expf(-gv[3]));
            c_reg = fg * c_reg + ig * gg;
            float hn = og * tanhf(c_reg);
            h_bits = f2tf(hn);
            out[((size_t)b2 * Tn + t) * (2 * Hn) + d * Hn + j0 + jj] = hn;
        }
        g_h[pw_][hidx] = h_bits;   // frozen h re-written when inactive

        flag_sync(d, myblk, base + 2 + s);
    }
}

// ---------------- mean pooling over valid length --------------------------
__global__ void pool_kernel(const int* __restrict__ lengths,
                            float* __restrict__ out) {
    const int c = blockIdx.x * 256 + threadIdx.x;
    const int b = blockIdx.y;
    const float* p = g_out1 + (size_t)b * Tn * (2 * Hn) + c;
    float s = 0.f;
    for (int t = 0; t < Tn; ++t) s += p[(size_t)t * (2 * Hn)];
    out[b * (2 * Hn) + c] = s / (float)lengths[b];
}

// ---------------- launch ---------------------------------------------------
extern "C" void kernel_launch(void* const* d_in, const int* in_sizes, int n_in,
                              void* d_out, int out_size) {
    const float* feats = (const float*)d_in[0];
    const int*   lens  = (const int*)  d_in[1];
    const float* encW  = (const float*)d_in[2];
    const float* encb  = (const float*)d_in[3];
    const float* wih0  = (const float*)d_in[4];
    const float* whh0  = (const float*)d_in[5];
    const float* b0    = (const float*)d_in[6];
    const float* wih1  = (const float*)d_in[7];
    const float* whh1  = (const float*)d_in[8];
    const float* b1    = (const float*)d_in[9];
    float* out = (float*)d_out;

    // opt-in to >48KB dynamic smem (attribute set, not an allocation)
    cudaFuncSetAttribute(rec_kernel,
                         cudaFuncAttributeMaxDynamicSharedMemorySize, REC_SMEM);
    cudaFuncSetAttribute(proj_gemm,
                         cudaFuncAttributeMaxDynamicSharedMemorySize, PROJ_SMEM);

    zero_kernel<<<2048, 256>>>();
    enc_kernel<<<Bsz * Tn, 256>>>(feats, encW, encb);

    // layer 0: project (K=256) then scan
    {
        dim3 grid(16, 128, 2);
        proj_gemm<<<grid, 256, PROJ_SMEM>>>(0, DENC, wih0, b0);
        rec_kernel<<<NB, 256, REC_SMEM>>>(whh0, lens, 0);
    }
    // layer 1: project (K=1024) then scan
    {
        dim3 grid(16, 128, 2);
        proj_gemm<<<grid, 256, PROJ_SMEM>>>(1, 2 * Hn, wih1, b1);
        rec_kernel<<<NB, 256, REC_SMEM>>>(whh1, lens, 1);
    }

    dim3 pg(4, Bsz);
    pool_kernel<<<pg, 256>>>(lens, out);
}

// round 14
// speedup vs baseline: 1.1830x; 1.0554x over previous
#include <cuda_runtime.h>
#include <math.h>

// Problem constants
#define Bsz   32
#define Tn    512
#define Jn    25
#define DENC  256
#define Hn    512
#define G4    2048      // 4*H
#define NB    128       // persistent recurrence grid (co-resident)
#define NB2   64        // blocks per direction

// ---------------- scratch (device globals; no allocations) ----------------
__device__ float    g_enc [Bsz * Tn * DENC];
__device__ float    g_xg  [2L * Tn * Bsz * G4];           // [d][t][b][4H]
__device__ float    g_out0[Bsz * Tn * 2 * Hn];            // [b][t][2H]
__device__ float    g_out1[Bsz * Tn * 2 * Hn];
__device__ __align__(16) unsigned g_h[2][2 * Bsz * Hn];   // tf32 bits, double-buffered
__device__ unsigned g_flag[2][NB2 * 32];                  // per-block flags, 128B apart

// ---------------- helpers --------------------------------------------------
__device__ __forceinline__ unsigned f2tf(float x) {
    unsigned u;
    asm("cvt.rna.tf32.f32 %0, %1;" : "=r"(u) : "f"(x));
    return u;
}

__device__ __forceinline__ void mma_tf32(float* c,
                                         unsigned a0, unsigned a1,
                                         unsigned a2, unsigned a3,
                                         unsigned b0, unsigned b1) {
    asm("mma.sync.aligned.m16n8k8.row.col.f32.tf32.tf32.f32 "
        "{%0,%1,%2,%3}, {%4,%5,%6,%7}, {%8,%9}, {%0,%1,%2,%3};"
        : "+f"(c[0]), "+f"(c[1]), "+f"(c[2]), "+f"(c[3])
        : "r"(a0), "r"(a1), "r"(a2), "r"(a3), "r"(b0), "r"(b1));
}

__device__ __forceinline__ void st_release_gpu(unsigned* p, unsigned v) {
    asm volatile("st.release.gpu.global.u32 [%0], %1;" :: "l"(p), "r"(v) : "memory");
}
__device__ __forceinline__ unsigned ld_acquire_gpu(const unsigned* p) {
    unsigned v;
    asm volatile("ld.acquire.gpu.global.u32 %0, [%1];" : "=r"(v) : "l"(p) : "memory");
    return v;
}
__device__ __forceinline__ void cp_async16(unsigned smem_addr_bytes,
                                           const void* gptr) {
    asm volatile("cp.async.cg.shared.global [%0], [%1], 16;"
                 :: "r"(smem_addr_bytes), "l"(gptr));
}

// ---------------- zero the output buffers ---------------------------------
__global__ void zero_kernel() {
    const int n4 = (Bsz * Tn * 2 * Hn) / 4;
    float4 z = make_float4(0.f, 0.f, 0.f, 0.f);
    for (int i = blockIdx.x * blockDim.x + threadIdx.x; i < n4;
         i += gridDim.x * blockDim.x) {
        reinterpret_cast<float4*>(g_out0)[i] = z;
        reinterpret_cast<float4*>(g_out1)[i] = z;
    }
}

// ---------------- encoder: relu(masked_xy @ W^T + b) ----------------------
__global__ void enc_kernel(const float* __restrict__ feats,
                           const float* __restrict__ W,
                           const float* __restrict__ bias) {
    __shared__ float xs[2 * Jn];
    const int bt  = blockIdx.x;
    const int tid = threadIdx.x;
    const float* f = feats + (size_t)bt * (Jn * 3);
    if (tid < Jn) {
        float c = (f[tid * 3 + 2] > 0.1f) ? 1.f : 0.f;
        xs[tid * 2 + 0] = f[tid * 3 + 0] * c;
        xs[tid * 2 + 1] = f[tid * 3 + 1] * c;
    }
    __syncthreads();
    const float* w = W + tid * (2 * Jn);
    float s = bias[tid];
#pragma unroll
    for (int k = 0; k < 2 * Jn; ++k) s += xs[k] * w[k];
    g_enc[(size_t)bt * DENC + tid] = fmaxf(s, 0.f);
}

// ---------------- input projection GEMM (tf32, k-tile 32 ping-pong) -------
// out_xg[d][t][b][g] = A[m=b*T+t,:K] . W[d][g,:K] + bias[d][g]
// block 128x128, 8 warps (2m x 4n), k-tile 32, 1 sync per tile
#define PROJ_SMEM (4 * 128 * 36 * 4)
extern __shared__ unsigned smp[];

__global__ void __launch_bounds__(256)
proj_gemm(int srcSel, int K, const float* __restrict__ W,
          const float* __restrict__ bias) {
    const float* A  = srcSel ? g_out0 : g_enc;
    const int d  = blockIdx.z;
    const float* Wd = W + (size_t)d * G4 * K;
    const float* bd = bias + d * G4;
    const int n0 = blockIdx.x * 128;
    const int m0 = blockIdx.y * 128;

    unsigned* As = smp;                   // [2][128*36]
    unsigned* Bs = smp + 2 * 128 * 36;

    const int tid  = threadIdx.x;
    const int lane = tid & 31;
    const int wid  = tid >> 5;
    const int wm   = (wid >> 2) * 64;
    const int wn   = (wid & 3) * 32;

    float acc[4][4][4];
#pragma unroll
    for (int mt = 0; mt < 4; ++mt)
#pragma unroll
        for (int nt = 0; nt < 4; ++nt)
#pragma unroll
            for (int i = 0; i < 4; ++i) acc[mt][nt][i] = 0.f;

    float4 ra[4], rw[4];
#pragma unroll
    for (int j = 0; j < 4; ++j) {
        int u = tid + j * 256, r = u >> 3, kq = (u & 7) << 2;
        ra[j] = *reinterpret_cast<const float4*>(A  + (size_t)(m0 + r) * K + kq);
        rw[j] = *reinterpret_cast<const float4*>(Wd + (size_t)(n0 + r) * K + kq);
    }

    const int KT = K >> 5;
    for (int kt = 0; kt < KT; ++kt) {
        const int p = kt & 1;
#pragma unroll
        for (int j = 0; j < 4; ++j) {
            int u = tid + j * 256, r = u >> 3, kq = (u & 7) << 2;
            uint4 ua, uw;
            ua.x = f2tf(ra[j].x); ua.y = f2tf(ra[j].y);
            ua.z = f2tf(ra[j].z); ua.w = f2tf(ra[j].w);
            uw.x = f2tf(rw[j].x); uw.y = f2tf(rw[j].y);
            uw.z = f2tf(rw[j].z); uw.w = f2tf(rw[j].w);
            *reinterpret_cast<uint4*>(As + p * 4608 + r * 36 + kq) = ua;
            *reinterpret_cast<uint4*>(Bs + p * 4608 + r * 36 + kq) = uw;
        }
        __syncthreads();     // single barrier per k-tile (ping-pong)

        if (kt + 1 < KT) {   // prefetch next tile while computing
            int kb = (kt + 1) * 32;
#pragma unroll
            for (int j = 0; j < 4; ++j) {
                int u = tid + j * 256, r = u >> 3, kq = (u & 7) << 2;
                ra[j] = *reinterpret_cast<const float4*>(A  + (size_t)(m0 + r) * K + kb + kq);
                rw[j] = *reinterpret_cast<const float4*>(Wd + (size_t)(n0 + r) * K + kb + kq);
            }
        }

        const unsigned* Ab = As + p * 4608;
        const unsigned* Bb = Bs + p * 4608;
#pragma unroll
        for (int kk = 0; kk < 32; kk += 8) {
            unsigned af[4][4], bf[4][2];
#pragma unroll
            for (int mt = 0; mt < 4; ++mt) {
                const unsigned* pp = Ab + (wm + mt * 16 + (lane >> 2)) * 36 + kk + (lane & 3);
                af[mt][0] = pp[0];
                af[mt][1] = pp[8 * 36];
                af[mt][2] = pp[4];
                af[mt][3] = pp[8 * 36 + 4];
            }
#pragma unroll
            for (int nt = 0; nt < 4; ++nt) {
                const unsigned* pp = Bb + (wn + nt * 8 + (lane >> 2)) * 36 + kk + (lane & 3);
                bf[nt][0] = pp[0];
                bf[nt][1] = pp[4];
            }
#pragma unroll
            for (int mt = 0; mt < 4; ++mt)
#pragma unroll
                for (int nt = 0; nt < 4; ++nt)
                    mma_tf32(acc[mt][nt], af[mt][0], af[mt][1], af[mt][2], af[mt][3],
                             bf[nt][0], bf[nt][1]);
        }
        __syncthreads();
    }

    // epilogue: bias + scatter to g_xg
#pragma unroll
    for (int mt = 0; mt < 4; ++mt) {
        int mrow0 = m0 + wm + mt * 16 + (lane >> 2);
#pragma unroll
        for (int nt = 0; nt < 4; ++nt) {
            int n = n0 + wn + nt * 8 + (lane & 3) * 2;
            float bv0 = bd[n], bv1 = bd[n + 1];
#pragma unroll
            for (int h = 0; h < 2; ++h) {
                int m  = mrow0 + h * 8;
                int t  = m & (Tn - 1);
                int bb = m >> 9;
                float* cp = g_xg + (((size_t)d * Tn + t) * Bsz + bb) * G4 + n;
                *reinterpret_cast<float2*>(cp) =
                    make_float2(acc[mt][nt][h * 2 + 0] + bv0,
                                acc[mt][nt][h * 2 + 1] + bv1);
            }
        }
    }
}

// ---------------- persistent bidirectional LSTM recurrence (tf32 MMA) -----
// R12 + fine-grained producer-subset sync: warp (mb,kc) consumes h columns
// kc*128..+127, produced by blocks kc*16..kc*16+15 ONLY. Lanes 0-15 poll
// those 16 flags; staging starts as soon as the warp's own producers are
// done (max-of-16 instead of max-of-64). Block-wide parity safety: the 8
// warps collectively cover all 64 producers before the phase-2 barrier.
// 2 __syncthreads per step (was 3).
#define REC_SMEM ((32 * 516 + 32 * 136) * 4)
extern __shared__ unsigned smr[];

__global__ void __launch_bounds__(256, 1)
rec_kernel(const float* __restrict__ whh,      // [2][4H][H]
           const int*   __restrict__ lengths,
           int outSel) {
    unsigned* hs   = smr;                          // [32 b][516] tf32 bits
    float*    part = (float*)(smr + 32 * 516);     // [32 b][136]
    float* out = outSel ? g_out1 : g_out0;
    const float* xg = g_xg;

    const int tid  = threadIdx.x;
    const int lane = tid & 31;
    const int wid  = tid >> 5;
    const int bx   = blockIdx.x;
    const int d    = bx >> 6;
    const int myblk = bx & 63;
    const int j0   = myblk << 3;
    const int mb   = wid & 1;             // batch half
    const int kc   = wid >> 1;            // K chunk (0..3), 128 k each

    // per-launch flag base + max length (uniform across all blocks)
    __shared__ unsigned s_base;
    __shared__ int s_maxlen;
    if (wid == 0) {
        int L = lengths[lane];
#pragma unroll
        for (int off = 16; off > 0; off >>= 1)
            L = max(L, __shfl_xor_sync(0xffffffffu, L, off));
        if (lane == 0) {
            s_maxlen = L;
            s_base = *(volatile unsigned*)&g_flag[d][myblk * 32];
        }
    }

    // stationary W fragments (B side): b0,b1 per (ks, nt=q)
    unsigned wb0[16][4], wb1[16][4];
    {
        const float* wdb = whh + (size_t)d * G4 * Hn;
#pragma unroll
        for (int ks = 0; ks < 16; ++ks)
#pragma unroll
            for (int nt = 0; nt < 4; ++nt) {
                const float* wp = wdb + (size_t)(nt * Hn + j0 + (lane >> 2)) * Hn
                                  + kc * 128 + ks * 8 + (lane & 3);
                wb0[ks][nt] = f2tf(wp[0]);
                wb1[ks][nt] = f2tf(wp[4]);
            }
    }

    // phase-2 identity: jj-major -> coalesced gmem
    const int jj = tid & 7;
    const int b2 = tid >> 3;              // 0..31
    const int len = lengths[b2];
    const int hidx = (d * Bsz + b2) * Hn + j0 + jj;
    float c_reg = 0.f;
    unsigned h_bits = 0u;
    g_h[0][hidx] = 0u;

    __syncthreads();
    const unsigned base = s_base;
    const int smax = s_maxlen;

    // announce h buffer 0 zeroed (consumers poll per-warp in the loop)
    if (tid == 0) st_release_gpu(&g_flag[d][myblk * 32], base + 1);

    // warp-private staging geometry: rows mb*16..+15, cols kc*128..+127
    const unsigned hs_warp_smem = (unsigned)__cvta_generic_to_shared(hs)
                                  + ((mb * 16) * 516 + kc * 128) * 4;
    const int h_warp_goff = (d * Bsz + mb * 16) * Hn + kc * 128;
    // my 16 producer flags: blocks kc*16 .. kc*16+15 of my direction
    unsigned* prod_flag = (lane < 16)
        ? &g_flag[d][(kc * 16 + lane) * 32] : (unsigned*)0;

    for (int s = 0; s < smax; ++s) {
        const int pr = s & 1, pw_ = pr ^ 1;
        const bool act = s < len;
        const int t = d ? (len - 1 - s) : s;

        // prefetch xg (independent of h; 32B-coalesced per (b,q) group)
        float xv0 = 0.f, xv1 = 0.f, xv2 = 0.f, xv3 = 0.f;
        if (act) {
            const float* xr = xg + (((size_t)d * Tn + t) * Bsz + b2) * G4 + j0 + jj;
            xv0 = xr[0];
            xv1 = xr[Hn];
            xv2 = xr[2 * Hn];
            xv3 = xr[3 * Hn];
        }

        // wait for MY 16 producers only, then stage own fragment region
        {
            const unsigned target = base + 1 + s;
            if (lane < 16) {
                while ((int)(ld_acquire_gpu(prod_flag) - target) < 0) { }
            }
            __syncwarp();
            const unsigned* hsrc = g_h[pr] + h_warp_goff;
#pragma unroll
            for (int i = 0; i < 16; ++i)
                cp_async16(hs_warp_smem + (i * 516 + lane * 4) * 4,
                           hsrc + i * Hn + lane * 4);
            asm volatile("cp.async.commit_group;" ::: "memory");
            asm volatile("cp.async.wait_group 0;" ::: "memory");
            __syncwarp();
        }

        float acc[4][4];
#pragma unroll
        for (int nt = 0; nt < 4; ++nt)
#pragma unroll
            for (int i = 0; i < 4; ++i) acc[nt][i] = 0.f;

#pragma unroll
        for (int ks = 0; ks < 16; ++ks) {
            const unsigned* hp = hs + (mb * 16 + (lane >> 2)) * 516
                                 + kc * 128 + ks * 8 + (lane & 3);
            unsigned a0 = hp[0];
            unsigned a2 = hp[4];
            unsigned a1 = hp[8 * 516];
            unsigned a3 = hp[8 * 516 + 4];
#pragma unroll
            for (int nt = 0; nt < 4; ++nt)
                mma_tf32(acc[nt], a0, a1, a2, a3, wb0[ks][nt], wb1[ks][nt]);
        }

        // write K-chunk partials: part[batch][kc*32 + q*8 + jcol]
        {
            const int b_lo = mb * 16 + (lane >> 2);
            const int col  = kc * 32 + ((lane & 3) << 1);
#pragma unroll
            for (int nt = 0; nt < 4; ++nt) {
                float* pp = part + b_lo * 136 + col + nt * 8;
                *reinterpret_cast<float2*>(pp) =
                    make_float2(acc[nt][0], acc[nt][1]);
                *reinterpret_cast<float2*>(pp + 8 * 136) =
                    make_float2(acc[nt][2], acc[nt][3]);
            }
        }
        __syncthreads();                 // partials complete

        // phase 2: reduce 4 K-chunk partials + gates (conflict-free reads)
        if (act) {
            const float* pb = part + b2 * 136 + jj;
            float gv[4];
#pragma unroll
            for (int q = 0; q < 4; ++q) {
                float v = (q == 0) ? xv0 : (q == 1) ? xv1 : (q == 2) ? xv2 : xv3;
#pragma unroll
                for (int k2 = 0; k2 < 4; ++k2)
                    v += pb[k2 * 32 + q * 8];
                gv[q] = v;
            }
            float ig = 1.f / (1.f + __expf(-gv[0]));
            float fg = 1.f / (1.f + __expf(-gv[1]));
            float gg = tanhf(gv[2]);
            float og = 1.f / (1.f + __expf(-gv[3]));
            c_reg = fg * c_reg + ig * gg;
            float hn = og * tanhf(c_reg);
            h_bits = f2tf(hn);
            g_h[pw_][hidx] = h_bits;     // critical-chain store first
            out[((size_t)b2 * Tn + t) * (2 * Hn) + d * Hn + j0 + jj] = hn;
        } else {
            g_h[pw_][hidx] = h_bits;     // frozen h re-written when inactive
        }
        __syncthreads();                 // all h stores done block-wide

        if (tid == 0)
            st_release_gpu(&g_flag[d][myblk * 32], base + 2 + s);
    }
}

// ---------------- mean pooling over valid length --------------------------
__global__ void pool_kernel(const int* __restrict__ lengths,
                            float* __restrict__ out) {
    const int c = blockIdx.x * 256 + threadIdx.x;
    const int b = blockIdx.y;
    const float* p = g_out1 + (size_t)b * Tn * (2 * Hn) + c;
    float s = 0.f;
    for (int t = 0; t < Tn; ++t) s += p[(size_t)t * (2 * Hn)];
    out[b * (2 * Hn) + c] = s / (float)lengths[b];
}

// ---------------- launch ---------------------------------------------------
extern "C" void kernel_launch(void* const* d_in, const int* in_sizes, int n_in,
                              void* d_out, int out_size) {
    const float* feats = (const float*)d_in[0];
    const int*   lens  = (const int*)  d_in[1];
    const float* encW  = (const float*)d_in[2];
    const float* encb  = (const float*)d_in[3];
    const float* wih0  = (const float*)d_in[4];
    const float* whh0  = (const float*)d_in[5];
    const float* b0    = (const float*)d_in[6];
    const float* wih1  = (const float*)d_in[7];
    const float* whh1  = (const float*)d_in[8];
    const float* b1    = (const float*)d_in[9];
    float* out = (float*)d_out;

    // opt-in to >48KB dynamic smem (attribute set, not an allocation)
    cudaFuncSetAttribute(rec_kernel,
                         cudaFuncAttributeMaxDynamicSharedMemorySize, REC_SMEM);
    cudaFuncSetAttribute(proj_gemm,
                         cudaFuncAttributeMaxDynamicSharedMemorySize, PROJ_SMEM);

    zero_kernel<<<2048, 256>>>();
    enc_kernel<<<Bsz * Tn, 256>>>(feats, encW, encb);

    // layer 0: project (K=256) then scan
    {
        dim3 grid(16, 128, 2);
        proj_gemm<<<grid, 256, PROJ_SMEM>>>(0, DENC, wih0, b0);
        rec_kernel<<<NB, 256, REC_SMEM>>>(whh0, lens, 0);
    }
    // layer 1: project (K=1024) then scan
    {
        dim3 grid(16, 128, 2);
        proj_gemm<<<grid, 256, PROJ_SMEM>>>(1, 2 * Hn, wih1, b1);
        rec_kernel<<<NB, 256, REC_SMEM>>>(whh1, lens, 1);
    }

    dim3 pg(4, Bsz);
    pool_kernel<<<pg, 256>>>(lens, out);
}